// round 4
// baseline (speedup 1.0000x reference)
// SAGNetworkHierarchical optimized kernel for GB300.
//
// THEORY / DESIGN NOTES (kept in-source to survive extraction quirks):
// * The reference returns ft.T which is exactly the MLP output; the whole
//   gat_conv branch and label edges are dead code. Skip them entirely.
// * 3 blocks of: GraphConv (norm=both) -> ReLU -> score GraphConv -> top-k
//   (k = ceil(0.5*n), exact, tie-break by lowest index) -> mean||max readout.
//   Then MLP 1280 -> 256(relu) -> 128(relu) -> 2048.
// * No node relabeling: cumulative alive mask over original ids. Readouts are
//   permutation invariant; edge masks match the reference's remap+mask chain.
// * CSR-by-dst built with int atomics (degree count + segment alloc + scatter).
//   Gather-SpMM warp-per-node, float4 per lane: g_hs (25 MB) stays L2
//   resident, ~410 MB of L2 traffic for block 0 at ~6300 B/cyc -> ~45 us.
// * Dense x@W as fp32 SIMT GEMM: 64-row x 128-col tile per 256-thread block,
//   X staged in shared, W rows broadcast from L1; ~1.6 GFLOP at block 0.
// * Exact k-th largest via 4-pass radix select on order-preserving uint keys
//   (single 1024-thread block), then ordered compaction with tie budget.
// Predicted dur_us: 300-600 (GEMM + SpMM dominated). Profile next round.

#include <cuda_runtime.h>
#include <math.h>

#define NN 50000
#define EE 800000

__device__ float    g_hs[NN * 128];
__device__ float    g_hrelu[NN * 128];
__device__ float    g_xcur[NN * 128];
__device__ float    g_hs2[NN];
__device__ float    g_score[NN];
__device__ unsigned g_key[NN];
__device__ int      g_deg_in[NN];
__device__ int      g_deg_out[NN];
__device__ int      g_fill[NN];
__device__ int      g_rowptr[NN];
__device__ int      g_csr[EE];
__device__ int      g_alive[NN];
__device__ int      g_list[2][NN];
__device__ float    g_ns[NN];
__device__ float    g_nd[NN];
__device__ float    g_mean[128];
__device__ float    g_bmax[3 * 128];
__device__ int      g_total;
__device__ unsigned g_T;
__device__ int      g_needed;
__device__ float    g_final[1280];
__device__ float    g_f1[256];
__device__ float    g_f2[128];

__device__ __forceinline__ unsigned okey(float f) {
    unsigned u = __float_as_uint(f);
    return (u & 0x80000000u) ? ~u : (u | 0x80000000u);
}
__device__ __forceinline__ void atomicMaxF(float* a, float v) {
    if (v >= 0.f) atomicMax((int*)a, __float_as_int(v));
    else          atomicMin((unsigned*)a, __float_as_uint(v));
}
// block-wide inclusive scan; blockDim.x must be 1024 (32 warps)
__device__ __forceinline__ int scanInc(int v, int* shw, int* tot) {
    int lane = threadIdx.x & 31, wid = threadIdx.x >> 5;
    int x = v;
#pragma unroll
    for (int o = 1; o < 32; o <<= 1) { int t = __shfl_up_sync(~0u, x, o); if (lane >= o) x += t; }
    if (lane == 31) shw[wid] = x;
    __syncthreads();
    if (wid == 0) {
        int w = shw[lane];
#pragma unroll
        for (int o = 1; o < 32; o <<= 1) { int t = __shfl_up_sync(~0u, w, o); if (lane >= o) w += t; }
        shw[lane] = w;
    }
    __syncthreads();
    int pre = wid ? shw[wid - 1] : 0;
    *tot = shw[31];
    __syncthreads();
    return x + pre;
}

__global__ void k_init() {
    int i = blockIdx.x * blockDim.x + threadIdx.x;
    if (i < NN) { g_alive[i] = 1; g_list[0][i] = i; }
    if (i < 128) g_mean[i] = 0.f;
    if (i < 3 * 128) g_bmax[i] = __int_as_float(0xff800000);
}
__global__ void k_zero() {
    int i = blockIdx.x * blockDim.x + threadIdx.x;
    if (i < NN) { g_deg_in[i] = 0; g_deg_out[i] = 0; g_fill[i] = 0; g_key[i] = 0u; }
    if (i == 0) g_total = 0;
}
__global__ void k_degree(const int* __restrict__ src, const int* __restrict__ dst) {
    int i = blockIdx.x * blockDim.x + threadIdx.x;
    if (i >= EE) return;
    int s = src[i], d = dst[i];
    if (g_alive[s] && g_alive[d]) { atomicAdd(&g_deg_out[s], 1); atomicAdd(&g_deg_in[d], 1); }
}
__global__ void k_alloc() {
    int i = blockIdx.x * blockDim.x + threadIdx.x;
    if (i >= NN) return;
    int d = g_deg_in[i];
    g_rowptr[i] = d ? atomicAdd(&g_total, d) : 0;
    g_ns[i] = 1.0f / sqrtf(fmaxf((float)g_deg_out[i], 1.0f));
    g_nd[i] = 1.0f / sqrtf(fmaxf((float)d, 1.0f));
}
__global__ void k_scatter(const int* __restrict__ src, const int* __restrict__ dst) {
    int i = blockIdx.x * blockDim.x + threadIdx.x;
    if (i >= EE) return;
    int s = src[i], d = dst[i];
    if (g_alive[s] && g_alive[d]) {
        int pos = atomicAdd(&g_fill[d], 1);
        g_csr[g_rowptr[d] + pos] = s;
    }
}
// hs[v] = (x[v] @ W) * ns[v] for alive rows; 64 rows x 128 cols per block.
// x == nullptr means read g_xcur.
__global__ __launch_bounds__(256) void k_gemm(const float* __restrict__ x,
                                              const float* __restrict__ W,
                                              int lin, int nA) {
    __shared__ float xs[64][128];
    __shared__ int rid[64];
    const float* xp = x ? x : (const float*)g_xcur;
    int tid = threadIdx.x;
    if (tid < 64) {
        int r = blockIdx.x * 64 + tid;
        rid[tid] = (r < nA) ? g_list[lin][r] : -1;
    }
    __syncthreads();
    for (int i = tid; i < 2048; i += 256) {
        int row = i >> 5, c4 = i & 31;
        int v = rid[row];
        float4 xv = make_float4(0.f, 0.f, 0.f, 0.f);
        if (v >= 0) xv = *(const float4*)&xp[v * 128 + c4 * 4];
        *(float4*)&xs[row][c4 * 4] = xv;
    }
    __syncthreads();
    int cg = tid & 31, rg = tid >> 5;
    float acc[8][4];
#pragma unroll
    for (int j = 0; j < 8; j++) { acc[j][0] = 0.f; acc[j][1] = 0.f; acc[j][2] = 0.f; acc[j][3] = 0.f; }
#pragma unroll 4
    for (int k = 0; k < 128; k++) {
        float4 w = *(const float4*)&W[k * 128 + cg * 4];
#pragma unroll
        for (int j = 0; j < 8; j++) {
            float xv = xs[rg * 8 + j][k];
            acc[j][0] += xv * w.x; acc[j][1] += xv * w.y;
            acc[j][2] += xv * w.z; acc[j][3] += xv * w.w;
        }
    }
#pragma unroll
    for (int j = 0; j < 8; j++) {
        int v = rid[rg * 8 + j];
        if (v >= 0) {
            float s = g_ns[v];
            float4 o = make_float4(acc[j][0] * s, acc[j][1] * s, acc[j][2] * s, acc[j][3] * s);
            *(float4*)&g_hs[v * 128 + cg * 4] = o;
        }
    }
}
// warp per node: aggregate in-neighbors of hs; hrelu = relu(agg*nd + cb);
// hs2 = dot(hrelu, sW) * ns
__global__ __launch_bounds__(256) void k_spmm_conv(const float* __restrict__ cb,
                                                   const float* __restrict__ sW,
                                                   int lin, int nA) {
    int gw = (blockIdx.x * blockDim.x + threadIdx.x) >> 5;
    int lane = threadIdx.x & 31;
    if (gw >= nA) return;
    int v = g_list[lin][gw];
    int s = g_rowptr[v], e = s + g_deg_in[v];
    float a0 = 0.f, a1 = 0.f, a2 = 0.f, a3 = 0.f;
    for (int i = s; i < e; i++) {
        int u = g_csr[i];
        float4 h = *(const float4*)&g_hs[u * 128 + lane * 4];
        a0 += h.x; a1 += h.y; a2 += h.z; a3 += h.w;
    }
    float ndv = g_nd[v];
    float4 b = *(const float4*)&cb[lane * 4];
    float4 hr;
    hr.x = fmaxf(fmaf(a0, ndv, b.x), 0.f);
    hr.y = fmaxf(fmaf(a1, ndv, b.y), 0.f);
    hr.z = fmaxf(fmaf(a2, ndv, b.z), 0.f);
    hr.w = fmaxf(fmaf(a3, ndv, b.w), 0.f);
    *(float4*)&g_hrelu[v * 128 + lane * 4] = hr;
    float4 w = *(const float4*)&sW[lane * 4];
    float sd = hr.x * w.x + hr.y * w.y + hr.z * w.z + hr.w * w.w;
#pragma unroll
    for (int o = 16; o; o >>= 1) sd += __shfl_down_sync(~0u, sd, o);
    if (lane == 0) g_hs2[v] = sd * g_ns[v];
}
__global__ __launch_bounds__(256) void k_spmm_score(const float* __restrict__ sb,
                                                    int lin, int nA) {
    int gw = (blockIdx.x * blockDim.x + threadIdx.x) >> 5;
    int lane = threadIdx.x & 31;
    if (gw >= nA) return;
    int v = g_list[lin][gw];
    int s = g_rowptr[v], e = s + g_deg_in[v];
    float sum = 0.f;
    for (int i = s + lane; i < e; i += 32) sum += g_hs2[g_csr[i]];
#pragma unroll
    for (int o = 16; o; o >>= 1) sum += __shfl_down_sync(~0u, sum, o);
    if (lane == 0) {
        float sc = fmaf(sum, g_nd[v], sb[0]);
        g_score[v] = sc;
        g_key[v] = okey(sc);
    }
}
// single block: exact k-th largest key among alive nodes -> g_T, g_needed
__global__ __launch_bounds__(1024) void k_select(int k) {
    __shared__ int hist[256];
    __shared__ unsigned sPref;
    __shared__ int sRem, cGT;
    int tid = threadIdx.x;
    if (tid == 0) { sPref = 0u; sRem = k; cGT = 0; }
    __syncthreads();
    for (int pass = 0; pass < 4; pass++) {
        unsigned HM = (pass == 0) ? 0u : (0xFFFFFFFFu << (32 - 8 * pass));
        int shift = 24 - 8 * pass;
        if (tid < 256) hist[tid] = 0;
        __syncthreads();
        unsigned pref = sPref;
        for (int i = tid; i < NN; i += 1024) {
            if (!g_alive[i]) continue;
            unsigned kv = g_key[i];
            if (((kv ^ pref) & HM) == 0u) atomicAdd(&hist[(kv >> shift) & 255], 1);
        }
        __syncthreads();
        if (tid == 0) {
            int rem = sRem, cum = 0;
            for (int d = 255; d >= 0; d--) {
                int c = hist[d];
                if (cum + c >= rem) { sPref = pref | ((unsigned)d << shift); sRem = rem - cum; break; }
                cum += c;
            }
        }
        __syncthreads();
    }
    unsigned T = sPref;
    int loc = 0;
    for (int i = tid; i < NN; i += 1024) if (g_alive[i] && g_key[i] > T) loc++;
    atomicAdd(&cGT, loc);
    __syncthreads();
    if (tid == 0) { g_T = T; g_needed = k - cGT; }
}
// single-block ordered compaction: keep key>T plus first needed ==T by index
__global__ __launch_bounds__(1024) void k_compact(int lout) {
    __shared__ int shw[32];
    __shared__ int cSel, cEq;
    unsigned T = g_T;
    int needed = g_needed;
    if (threadIdx.x == 0) { cSel = 0; cEq = 0; }
    __syncthreads();
    for (int base = 0; base < NN; base += 1024) {
        int i = base + threadIdx.x;
        int alive = (i < NN) ? g_alive[i] : 0;
        unsigned kv = alive ? g_key[i] : 0u;
        int eq = alive && (kv == T);
        int tEq, tSel;
        int eqInc = scanInc(eq, shw, &tEq);
        int eqBefore = cEq + eqInc - eq;
        int sel = (alive && (kv > T)) || (eq && eqBefore < needed);
        int selInc = scanInc(sel, shw, &tSel);
        int pos = cSel + selInc - 1;
        if (i < NN) {
            if (sel) g_list[lout][pos] = i;
            else g_alive[i] = 0;
        }
        __syncthreads();
        if (threadIdx.x == 0) { cSel += tSel; cEq += tEq; }
        __syncthreads();
    }
}
// gated features + readout accumulation: 64 nodes per block, thread per column
__global__ __launch_bounds__(128) void k_pool(int b, int lin, int kb, float invk) {
    __shared__ float sth[64];
    int c = threadIdx.x;
    int base = blockIdx.x * 64;
    int lim = min(64, kb - base);
    if (c < 64 && c < lim) {
        int v = g_list[lin][base + c];
        sth[c] = tanhf(g_score[v]);
    }
    __syncthreads();
    float msum = 0.f, mmax = __int_as_float(0xff800000);
    for (int j = 0; j < lim; j++) {
        int v = g_list[lin][base + j];
        float val = g_hrelu[v * 128 + c] * sth[j];
        g_xcur[v * 128 + c] = val;
        msum += val;
        mmax = fmaxf(mmax, val);
    }
    atomicAdd(&g_mean[c], msum * invk);
    atomicMaxF(&g_bmax[b * 128 + c], mmax);
}
__global__ void k_assemble(const float* __restrict__ seq) {
    for (int i = threadIdx.x; i < 1280; i += blockDim.x) {
        float v;
        if (i < 128)      v = g_mean[i];
        else if (i < 256) v = g_bmax[i - 128] + g_bmax[128 + (i - 128)] + g_bmax[256 + (i - 128)];
        else              v = seq[i - 256];
        g_final[i] = v;
    }
}
__global__ __launch_bounds__(256) void k_lin1(const float* __restrict__ W, const float* __restrict__ b) {
    __shared__ float fin[1280];
    int t = threadIdx.x;
    for (int i = t; i < 1280; i += 256) fin[i] = g_final[i];
    __syncthreads();
    float acc = b[t];
    for (int k = 0; k < 1280; k++) acc = fmaf(fin[k], W[k * 256 + t], acc);
    g_f1[t] = fmaxf(acc, 0.f);
}
__global__ __launch_bounds__(128) void k_lin2(const float* __restrict__ W, const float* __restrict__ b) {
    __shared__ float f1[256];
    int t = threadIdx.x;
    for (int i = t; i < 256; i += 128) f1[i] = g_f1[i];
    __syncthreads();
    float acc = b[t];
    for (int k = 0; k < 256; k++) acc = fmaf(f1[k], W[k * 128 + t], acc);
    g_f2[t] = fmaxf(acc, 0.f);
}
__global__ __launch_bounds__(256) void k_lin3(const float* __restrict__ W, const float* __restrict__ b,
                                              float* __restrict__ out) {
    __shared__ float f2[128];
    int t = threadIdx.x;
    if (t < 128) f2[t] = g_f2[t];
    __syncthreads();
    int o = blockIdx.x * 256 + t;
    float acc = b[o];
    for (int k = 0; k < 128; k++) acc = fmaf(f2[k], W[k * 2048 + o], acc);
    out[o] = acc;
}

extern "C" void kernel_launch(void* const* d_in, const int* in_sizes, int n_in,
                              void* d_out, int out_size) {
    const float* feat = (const float*)d_in[0];
    const float* seq  = (const float*)d_in[1];
    const int*   src  = (const int*)d_in[2];
    const int*   dst  = (const int*)d_in[3];
    // d_in[4], d_in[5]: label_src/label_dst -> dead code, unused
    const float* cW[3] = {(const float*)d_in[6],  (const float*)d_in[10], (const float*)d_in[14]};
    const float* cb[3] = {(const float*)d_in[7],  (const float*)d_in[11], (const float*)d_in[15]};
    const float* sW[3] = {(const float*)d_in[8],  (const float*)d_in[12], (const float*)d_in[16]};
    const float* sb[3] = {(const float*)d_in[9],  (const float*)d_in[13], (const float*)d_in[17]};
    const float* l1W = (const float*)d_in[18];
    const float* l1b = (const float*)d_in[19];
    const float* l2W = (const float*)d_in[20];
    const float* l2b = (const float*)d_in[21];
    const float* l3W = (const float*)d_in[22];
    const float* l3b = (const float*)d_in[23];
    float* out = (float*)d_out;

    // k per block: ceil(0.5*n): 50000 -> 25000 -> 12500 -> 6250
    const int nAv[3] = {50000, 25000, 12500};
    const int kbv[3] = {25000, 12500, 6250};

    k_init<<<(NN + 255) / 256, 256>>>();
    for (int b = 0; b < 3; b++) {
        int nA = nAv[b], kb = kbv[b];
        int lin = b & 1, lout = 1 - lin;
        k_zero<<<(NN + 255) / 256, 256>>>();
        k_degree<<<(EE + 255) / 256, 256>>>(src, dst);
        k_alloc<<<(NN + 255) / 256, 256>>>();
        k_scatter<<<(EE + 255) / 256, 256>>>(src, dst);
        k_gemm<<<(nA + 63) / 64, 256>>>(b == 0 ? feat : (const float*)0, cW[b], lin, nA);
        k_spmm_conv<<<(nA + 7) / 8, 256>>>(cb[b], sW[b], lin, nA);
        k_spmm_score<<<(nA + 7) / 8, 256>>>(sb[b], lin, nA);
        k_select<<<1, 1024>>>(kb);
        k_compact<<<1, 1024>>>(lout);
        k_pool<<<(kb + 63) / 64, 128>>>(b, lout, kb, 1.0f / (float)kb);
    }
    k_assemble<<<1, 256>>>(seq);
    k_lin1<<<1, 256>>>(l1W, l1b);
    k_lin2<<<1, 128>>>(l2W, l2b);
    k_lin3<<<8, 256>>>(l3W, l3b, out);
}

// round 5
// speedup vs baseline: 1.5749x; 1.5749x over previous
// SAGNetworkHierarchical GB300 kernel, round 5.
// R4 passed at 825 us (rel_err 0). This round: parallel top-k selection
// (grid histogram + small finish), edge-list compaction across blocks,
// g_xcur elimination (row-scale commutes with x@W), wider lin1.
#include <cuda_runtime.h>
#include <math.h>

#define NN 50000
#define EE 800000
#define HB 65536
#define TCAP 6144

__device__ float    g_hs[NN * 128];
__device__ float    g_hrelu[NN * 128];
__device__ float    g_hs2[NN];
__device__ float    g_score[NN];
__device__ float    g_th[NN];
__device__ unsigned g_key[NN];
__device__ int      g_deg_in[NN];
__device__ int      g_deg_out[NN];
__device__ int      g_fill[NN];
__device__ int      g_rowptr[NN];
__device__ int      g_csr[EE];
__device__ int      g_alive[NN];
__device__ int      g_list[2][NN];
__device__ float    g_ns[NN];
__device__ float    g_nd[NN];
__device__ float    g_mean[128];
__device__ float    g_bmax[3 * 128];
__device__ int      g_total;
__device__ int      g_hist[HB];
__device__ int      g_bucketHi;
__device__ int      g_cntAbove;
__device__ int      g_selcnt;
__device__ int      g_candcnt;
__device__ unsigned g_candk[NN];
__device__ int      g_candv[NN];
__device__ int      g_e1s[EE], g_e1d[EE];
__device__ int      g_e2s[EE], g_e2d[EE];
__device__ int      g_e1n, g_e2n;
__device__ float    g_final[1280];
__device__ float    g_f1[256];
__device__ float    g_f2[128];

__device__ __forceinline__ unsigned okey(float f) {
    unsigned u = __float_as_uint(f);
    return (u & 0x80000000u) ? ~u : (u | 0x80000000u);
}
__device__ __forceinline__ void atomicMaxF(float* a, float v) {
    if (v >= 0.f) atomicMax((int*)a, __float_as_int(v));
    else          atomicMin((unsigned*)a, __float_as_uint(v));
}

__global__ void k_init() {
    int i = blockIdx.x * blockDim.x + threadIdx.x;
    if (i < NN) { g_alive[i] = 1; g_list[0][i] = i; }
    if (i < 128) g_mean[i] = 0.f;
    if (i < 3 * 128) g_bmax[i] = __int_as_float(0xff800000);
}
// zeroE: 0 none, 1 zero g_e1n, 2 zero g_e2n. Launch with >= HB threads.
__global__ void k_zero(int zeroE) {
    int i = blockIdx.x * blockDim.x + threadIdx.x;
    if (i < NN) { g_deg_in[i] = 0; g_deg_out[i] = 0; g_fill[i] = 0; }
    if (i < HB) g_hist[i] = 0;
    if (i == 0) {
        g_total = 0; g_selcnt = 0; g_candcnt = 0;
        if (zeroE == 1) g_e1n = 0; else if (zeroE == 2) g_e2n = 0;
    }
}
// block 0: all nodes alive, no checks
__global__ void k_degree0(const int* __restrict__ src, const int* __restrict__ dst) {
    int i = blockIdx.x * blockDim.x + threadIdx.x;
    if (i >= EE) return;
    atomicAdd(&g_deg_out[src[i]], 1);
    atomicAdd(&g_deg_in[dst[i]], 1);
}
// blocks 1/2: filter by alive, count degrees, append survivors (warp-aggregated)
__global__ void k_degcomp(const int* __restrict__ es, const int* __restrict__ ed, int mode) {
    int i = blockIdx.x * blockDim.x + threadIdx.x;
    int cnt = (mode == 1) ? EE : g_e1n;
    int s = 0, d = 0; bool ok = false;
    if (i < cnt) {
        if (mode == 1) { s = es[i]; d = ed[i]; }
        else           { s = g_e1s[i]; d = g_e1d[i]; }
        ok = g_alive[s] && g_alive[d];
    }
    if (ok) { atomicAdd(&g_deg_out[s], 1); atomicAdd(&g_deg_in[d], 1); }
    unsigned m = __ballot_sync(~0u, ok);
    if (m) {
        int lane = threadIdx.x & 31;
        int ldr = __ffs(m) - 1;
        int base;
        if (lane == ldr) base = atomicAdd((mode == 1) ? &g_e1n : &g_e2n, __popc(m));
        base = __shfl_sync(~0u, base, ldr);
        if (ok) {
            int p = base + __popc(m & ((1u << lane) - 1));
            if (mode == 1) { g_e1s[p] = s; g_e1d[p] = d; }
            else           { g_e2s[p] = s; g_e2d[p] = d; }
        }
    }
}
__global__ void k_alloc() {
    int i = blockIdx.x * blockDim.x + threadIdx.x;
    if (i >= NN) return;
    int d = g_deg_in[i];
    g_rowptr[i] = d ? atomicAdd(&g_total, d) : 0;
    g_ns[i] = 1.0f / sqrtf(fmaxf((float)g_deg_out[i], 1.0f));
    g_nd[i] = 1.0f / sqrtf(fmaxf((float)d, 1.0f));
}
// mode 0: src/dst (EE, unchecked); 1: E1 list; 2: E2 list
__global__ void k_scatter(const int* __restrict__ es, const int* __restrict__ ed, int mode) {
    int i = blockIdx.x * blockDim.x + threadIdx.x;
    int cnt = (mode == 0) ? EE : (mode == 1 ? g_e1n : g_e2n);
    if (i >= cnt) return;
    int s, d;
    if (mode == 0)      { s = es[i];   d = ed[i];   }
    else if (mode == 1) { s = g_e1s[i]; d = g_e1d[i]; }
    else                { s = g_e2s[i]; d = g_e2d[i]; }
    int pos = atomicAdd(&g_fill[d], 1);
    g_csr[g_rowptr[d] + pos] = s;
}
// hs[v] = (x[v] @ W) * ns[v] * (useTh ? th[v] : 1); x==null means g_hrelu
__global__ __launch_bounds__(256) void k_gemm(const float* __restrict__ x,
                                              const float* __restrict__ W,
                                              int lin, int nA, int useTh) {
    __shared__ float xs[64][128];
    __shared__ int rid[64];
    const float* xp = x ? x : (const float*)g_hrelu;
    int tid = threadIdx.x;
    if (tid < 64) {
        int r = blockIdx.x * 64 + tid;
        rid[tid] = (r < nA) ? g_list[lin][r] : -1;
    }
    __syncthreads();
    for (int i = tid; i < 2048; i += 256) {
        int row = i >> 5, c4 = i & 31;
        int v = rid[row];
        float4 xv = make_float4(0.f, 0.f, 0.f, 0.f);
        if (v >= 0) xv = *(const float4*)&xp[v * 128 + c4 * 4];
        *(float4*)&xs[row][c4 * 4] = xv;
    }
    __syncthreads();
    int cg = tid & 31, rg = tid >> 5;
    float acc[8][4];
#pragma unroll
    for (int j = 0; j < 8; j++) { acc[j][0] = 0.f; acc[j][1] = 0.f; acc[j][2] = 0.f; acc[j][3] = 0.f; }
#pragma unroll 4
    for (int k = 0; k < 128; k++) {
        float4 w = *(const float4*)&W[k * 128 + cg * 4];
#pragma unroll
        for (int j = 0; j < 8; j++) {
            float xv = xs[rg * 8 + j][k];
            acc[j][0] += xv * w.x; acc[j][1] += xv * w.y;
            acc[j][2] += xv * w.z; acc[j][3] += xv * w.w;
        }
    }
#pragma unroll
    for (int j = 0; j < 8; j++) {
        int v = rid[rg * 8 + j];
        if (v >= 0) {
            float s = g_ns[v] * (useTh ? g_th[v] : 1.0f);
            float4 o = make_float4(acc[j][0] * s, acc[j][1] * s, acc[j][2] * s, acc[j][3] * s);
            *(float4*)&g_hs[v * 128 + cg * 4] = o;
        }
    }
}
__global__ __launch_bounds__(256) void k_spmm_conv(const float* __restrict__ cb,
                                                   const float* __restrict__ sW,
                                                   int lin, int nA) {
    int gw = (blockIdx.x * blockDim.x + threadIdx.x) >> 5;
    int lane = threadIdx.x & 31;
    if (gw >= nA) return;
    int v = g_list[lin][gw];
    int s = g_rowptr[v], e = s + g_deg_in[v];
    float a0 = 0.f, a1 = 0.f, a2 = 0.f, a3 = 0.f;
    for (int i = s; i < e; i++) {
        int u = g_csr[i];
        float4 h = *(const float4*)&g_hs[u * 128 + lane * 4];
        a0 += h.x; a1 += h.y; a2 += h.z; a3 += h.w;
    }
    float ndv = g_nd[v];
    float4 b = *(const float4*)&cb[lane * 4];
    float4 hr;
    hr.x = fmaxf(fmaf(a0, ndv, b.x), 0.f);
    hr.y = fmaxf(fmaf(a1, ndv, b.y), 0.f);
    hr.z = fmaxf(fmaf(a2, ndv, b.z), 0.f);
    hr.w = fmaxf(fmaf(a3, ndv, b.w), 0.f);
    *(float4*)&g_hrelu[v * 128 + lane * 4] = hr;
    float4 w = *(const float4*)&sW[lane * 4];
    float sd = hr.x * w.x + hr.y * w.y + hr.z * w.z + hr.w * w.w;
#pragma unroll
    for (int o = 16; o; o >>= 1) sd += __shfl_down_sync(~0u, sd, o);
    if (lane == 0) g_hs2[v] = sd * g_ns[v];
}
__global__ __launch_bounds__(256) void k_spmm_score(const float* __restrict__ sb,
                                                    int lin, int nA) {
    int gw = (blockIdx.x * blockDim.x + threadIdx.x) >> 5;
    int lane = threadIdx.x & 31;
    if (gw >= nA) return;
    int v = g_list[lin][gw];
    int s = g_rowptr[v], e = s + g_deg_in[v];
    float sum = 0.f;
    for (int i = s + lane; i < e; i += 32) sum += g_hs2[g_csr[i]];
#pragma unroll
    for (int o = 16; o; o >>= 1) sum += __shfl_down_sync(~0u, sum, o);
    if (lane == 0) {
        float sc = fmaf(sum, g_nd[v], sb[0]);
        g_score[v] = sc;
        g_key[v] = okey(sc);
    }
}
__global__ void k_hist(int lin, int nA) {
    int i = blockIdx.x * blockDim.x + threadIdx.x;
    if (i >= nA) return;
    atomicAdd(&g_hist[g_key[g_list[lin][i]] >> 16], 1);
}
// single block: find 16-bit bucket containing the k-th largest key
__global__ __launch_bounds__(1024) void k_pick(int k) {
    __shared__ int A[1024];
    int t = threadIdx.x;
    int base = t * 64;
    int s = 0;
    for (int b = 0; b < 64; b++) s += g_hist[base + b];
    A[t] = s;
    __syncthreads();
    for (int off = 1; off < 1024; off <<= 1) {
        int w = A[t] + ((t + off < 1024) ? A[t + off] : 0);
        __syncthreads();
        A[t] = w;
        __syncthreads();
    }
    int above = A[t] - s;  // count of keys in buckets strictly above this chunk
    if (above < k && above + s >= k) {
        int cum = above;
        for (int b = 63; b >= 0; b--) {
            int h = g_hist[base + b];
            if (cum + h >= k) { g_bucketHi = base + b; g_cntAbove = cum; break; }
            cum += h;
        }
    }
}
// split: hi>bucket -> selected; hi==bucket -> candidate; else killed
__global__ void k_cand(int lin, int lout, int nA) {
    int i = blockIdx.x * blockDim.x + threadIdx.x;
    int bh = g_bucketHi;
    int v = -1; unsigned key = 0; int hi = -1;
    if (i < nA) { v = g_list[lin][i]; key = g_key[v]; hi = (int)(key >> 16); }
    bool gt = (i < nA) && (hi > bh);
    bool eq = (i < nA) && (hi == bh);
    int lane = threadIdx.x & 31;
    unsigned m = __ballot_sync(~0u, gt);
    if (m) {
        int ldr = __ffs(m) - 1; int base;
        if (lane == ldr) base = atomicAdd(&g_selcnt, __popc(m));
        base = __shfl_sync(~0u, base, ldr);
        if (gt) g_list[lout][base + __popc(m & ((1u << lane) - 1))] = v;
    }
    unsigned m2 = __ballot_sync(~0u, eq);
    if (m2) {
        int ldr = __ffs(m2) - 1; int base;
        if (lane == ldr) base = atomicAdd(&g_candcnt, __popc(m2));
        base = __shfl_sync(~0u, base, ldr);
        if (eq) {
            int p = base + __popc(m2 & ((1u << lane) - 1));
            g_candk[p] = key; g_candv[p] = v;
        }
    }
    if (i < nA && !gt && !eq) { g_alive[v] = 0; g_key[v] = 0u; }
}
// single block: refine low 16 bits over candidates, handle ties by lowest id
__global__ __launch_bounds__(1024) void k_finish(int lout, int k) {
    __shared__ int hist[256];
    __shared__ int sh_b1, sh_rem1, sh_b0, sh_needed, sh_tc;
    __shared__ int tiebuf[TCAP];
    int tid = threadIdx.x;
    int C = g_candcnt;
    int kp = k - g_cntAbove;  // >= 1
    for (int i = tid; i < 256; i += 1024) hist[i] = 0;
    if (tid == 0) sh_tc = 0;
    __syncthreads();
    for (int i = tid; i < C; i += 1024) atomicAdd(&hist[(g_candk[i] >> 8) & 255], 1);
    __syncthreads();
    if (tid == 0) {
        int cum = 0;
        for (int b = 255; b >= 0; b--) {
            int h = hist[b];
            if (cum + h >= kp) { sh_b1 = b; sh_rem1 = kp - cum; break; }
            cum += h;
        }
    }
    __syncthreads();
    int b1 = sh_b1, rem1 = sh_rem1;
    for (int i = tid; i < 256; i += 1024) hist[i] = 0;
    __syncthreads();
    for (int i = tid; i < C; i += 1024) {
        unsigned kk = g_candk[i];
        if ((int)((kk >> 8) & 255) == b1) atomicAdd(&hist[kk & 255], 1);
    }
    __syncthreads();
    if (tid == 0) {
        int cum = 0;
        for (int b = 255; b >= 0; b--) {
            int h = hist[b];
            if (cum + h >= rem1) { sh_b0 = b; sh_needed = rem1 - cum; break; }
            cum += h;
        }
    }
    __syncthreads();
    unsigned lo_t = ((unsigned)b1 << 8) | (unsigned)sh_b0;
    int needed = sh_needed;  // >= 1
    for (int i = tid; i < C; i += 1024) {
        unsigned lo = g_candk[i] & 0xFFFFu;
        int v = g_candv[i];
        if (lo > lo_t) {
            int p = atomicAdd(&g_selcnt, 1);
            g_list[lout][p] = v;
        } else if (lo < lo_t) {
            g_alive[v] = 0; g_key[v] = 0u;
        } else {
            int p = atomicAdd(&sh_tc, 1);
            if (p < TCAP) tiebuf[p] = v;
        }
    }
    __syncthreads();
    int T = sh_tc;
    if (T <= needed) {
        // all ties selected
        for (int i = tid; i < C; i += 1024) {
            if ((g_candk[i] & 0xFFFFu) == lo_t) {
                int p = atomicAdd(&g_selcnt, 1);
                g_list[lout][p] = g_candv[i];
            }
        }
    } else if (T <= TCAP) {
        for (int j = tid; j < T; j += 1024) {
            int vj = tiebuf[j];
            int r = 0;
            for (int q = 0; q < T; q++) r += (tiebuf[q] < vj);
            if (r < needed) {
                int p = atomicAdd(&g_selcnt, 1);
                g_list[lout][p] = vj;
            } else { g_alive[vj] = 0; g_key[vj] = 0u; }
        }
    } else {
        // fallback: rank each tie by scanning the candidate buffer
        for (int i = tid; i < C; i += 1024) {
            if ((g_candk[i] & 0xFFFFu) != lo_t) continue;
            int vi = g_candv[i];
            int r = 0;
            for (int q = 0; q < C; q++)
                if ((g_candk[q] & 0xFFFFu) == lo_t && g_candv[q] < vi) r++;
            if (r < needed) {
                int p = atomicAdd(&g_selcnt, 1);
                g_list[lout][p] = vi;
            } else { g_alive[vi] = 0; g_key[vi] = 0u; }
        }
    }
}
// readout (mean/max of gated features) + store th; no g_xcur materialization
__global__ __launch_bounds__(128) void k_pool(int b, int lout, int kb, float invk) {
    __shared__ float sth[64];
    __shared__ int sv[64];
    int c = threadIdx.x;
    int base = blockIdx.x * 64;
    int lim = min(64, kb - base);
    if (c < 64 && c < lim) {
        int v = g_list[lout][base + c];
        float th = tanhf(g_score[v]);
        sth[c] = th; sv[c] = v; g_th[v] = th;
    }
    __syncthreads();
    float msum = 0.f, mmax = __int_as_float(0xff800000);
    for (int j = 0; j < lim; j++) {
        float val = g_hrelu[sv[j] * 128 + c] * sth[j];
        msum += val;
        mmax = fmaxf(mmax, val);
    }
    atomicAdd(&g_mean[c], msum * invk);
    atomicMaxF(&g_bmax[b * 128 + c], mmax);
}
__global__ void k_assemble(const float* __restrict__ seq) {
    for (int i = threadIdx.x; i < 1280; i += blockDim.x) {
        float v;
        if (i < 128)      v = g_mean[i];
        else if (i < 256) v = g_bmax[i - 128] + g_bmax[128 + (i - 128)] + g_bmax[256 + (i - 128)];
        else              v = seq[i - 256];
        g_final[i] = v;
    }
}
__global__ __launch_bounds__(1024) void k_lin1(const float* __restrict__ W, const float* __restrict__ b) {
    __shared__ float fin[1280];
    __shared__ float red[1024];
    int t = threadIdx.x;
    for (int i = t; i < 1280; i += 1024) fin[i] = g_final[i];
    __syncthreads();
    int o = t & 255, part = t >> 8;
    float acc = 0.f;
    int k0 = part * 320;
    for (int k = k0; k < k0 + 320; k++) acc = fmaf(fin[k], W[k * 256 + o], acc);
    red[t] = acc;
    __syncthreads();
    if (t < 256) {
        float s = red[t] + red[t + 256] + red[t + 512] + red[t + 768] + b[t];
        g_f1[t] = fmaxf(s, 0.f);
    }
}
__global__ __launch_bounds__(128) void k_lin2(const float* __restrict__ W, const float* __restrict__ b) {
    __shared__ float f1[256];
    int t = threadIdx.x;
    for (int i = t; i < 256; i += 128) f1[i] = g_f1[i];
    __syncthreads();
    float acc = b[t];
    for (int k = 0; k < 256; k++) acc = fmaf(f1[k], W[k * 128 + t], acc);
    g_f2[t] = fmaxf(acc, 0.f);
}
__global__ __launch_bounds__(256) void k_lin3(const float* __restrict__ W, const float* __restrict__ b,
                                              float* __restrict__ out) {
    __shared__ float f2[128];
    int t = threadIdx.x;
    if (t < 128) f2[t] = g_f2[t];
    __syncthreads();
    int o = blockIdx.x * 256 + t;
    float acc = b[o];
    for (int k = 0; k < 128; k++) acc = fmaf(f2[k], W[k * 2048 + o], acc);
    out[o] = acc;
}

extern "C" void kernel_launch(void* const* d_in, const int* in_sizes, int n_in,
                              void* d_out, int out_size) {
    const float* feat = (const float*)d_in[0];
    const float* seq  = (const float*)d_in[1];
    const int*   src  = (const int*)d_in[2];
    const int*   dst  = (const int*)d_in[3];
    const float* cW[3] = {(const float*)d_in[6],  (const float*)d_in[10], (const float*)d_in[14]};
    const float* cb[3] = {(const float*)d_in[7],  (const float*)d_in[11], (const float*)d_in[15]};
    const float* sW[3] = {(const float*)d_in[8],  (const float*)d_in[12], (const float*)d_in[16]};
    const float* sb[3] = {(const float*)d_in[9],  (const float*)d_in[13], (const float*)d_in[17]};
    const float* l1W = (const float*)d_in[18];
    const float* l1b = (const float*)d_in[19];
    const float* l2W = (const float*)d_in[20];
    const float* l2b = (const float*)d_in[21];
    const float* l3W = (const float*)d_in[22];
    const float* l3b = (const float*)d_in[23];
    float* out = (float*)d_out;

    const int nAv[3] = {50000, 25000, 12500};
    const int kbv[3] = {25000, 12500, 6250};
    const int ZGRID = (HB + 255) / 256;
    const int EGRID = (EE + 255) / 256;

    k_init<<<(NN + 255) / 256, 256>>>();
    for (int b = 0; b < 3; b++) {
        int nA = nAv[b], kb = kbv[b];
        int lin = b & 1, lout = 1 - lin;
        k_zero<<<ZGRID, 256>>>(b);  // b==1 zeroes e1n, b==2 zeroes e2n
        if (b == 0) {
            k_degree0<<<EGRID, 256>>>(src, dst);
        } else {
            k_degcomp<<<EGRID, 256>>>(src, dst, b);  // mode 1 reads src/dst, mode 2 reads E1
        }
        k_alloc<<<(NN + 255) / 256, 256>>>();
        k_scatter<<<EGRID, 256>>>(src, dst, b);      // mode 0/1/2
        k_gemm<<<(nA + 63) / 64, 256>>>(b == 0 ? feat : (const float*)0, cW[b], lin, nA, b > 0);
        k_spmm_conv<<<(nA + 7) / 8, 256>>>(cb[b], sW[b], lin, nA);
        k_spmm_score<<<(nA + 7) / 8, 256>>>(sb[b], lin, nA);
        k_hist<<<(nA + 255) / 256, 256>>>(lin, nA);
        k_pick<<<1, 1024>>>(kb);
        k_cand<<<(nA + 255) / 256, 256>>>(lin, lout, nA);
        k_finish<<<1, 1024>>>(lout, kb);
        k_pool<<<(kb + 63) / 64, 128>>>(b, lout, kb, 1.0f / (float)kb);
    }
    k_assemble<<<1, 256>>>(seq);
    k_lin1<<<1, 1024>>>(l1W, l1b);
    k_lin2<<<1, 128>>>(l2W, l2b);
    k_lin3<<<8, 256>>>(l3W, l3b, out);
}

// round 6
// speedup vs baseline: 1.6584x; 1.0530x over previous
// SAGNetworkHierarchical GB300 kernel, round 6.
// R5: 524 us. This round: warp-aggregated rowptr alloc, atomic-free scatter
// (ordinals captured in degree pass), launch fusion (init+zero, hist->score,
// zeroing->pool, assemble->lin1, lin2+lin3), gemm moved to profiled slot.
#include <cuda_runtime.h>
#include <math.h>

#define NN 50000
#define EE 800000
#define HB 65536
#define TCAP 6144

__device__ float    g_hs[NN * 128];
__device__ float    g_hrelu[NN * 128];
__device__ float    g_hs2[NN];
__device__ float    g_score[NN];
__device__ float    g_th[NN];
__device__ unsigned g_key[NN];
__device__ int      g_deg_in[NN];
__device__ int      g_deg_out[NN];
__device__ int      g_rowptr[NN];
__device__ int      g_csr[EE];
__device__ int      g_ord[EE];
__device__ int      g_alive[NN];
__device__ int      g_list[2][NN];
__device__ float    g_ns[NN];
__device__ float    g_nd[NN];
__device__ float    g_mean[128];
__device__ float    g_bmax[3 * 128];
__device__ int      g_total;
__device__ int      g_hist[HB];
__device__ int      g_bucketHi;
__device__ int      g_cntAbove;
__device__ int      g_selcnt;
__device__ int      g_candcnt;
__device__ unsigned g_candk[NN];
__device__ int      g_candv[NN];
__device__ int      g_e1s[EE], g_e1d[EE], g_e1o[EE];
__device__ int      g_e2s[EE], g_e2d[EE], g_e2o[EE];
__device__ int      g_e1n, g_e2n;
__device__ float    g_f1[256];

__device__ __forceinline__ unsigned okey(float f) {
    unsigned u = __float_as_uint(f);
    return (u & 0x80000000u) ? ~u : (u | 0x80000000u);
}
__device__ __forceinline__ void atomicMaxF(float* a, float v) {
    if (v >= 0.f) atomicMax((int*)a, __float_as_int(v));
    else          atomicMin((unsigned*)a, __float_as_uint(v));
}

// merged init + zero for block 0
__global__ void k_init0() {
    int i = blockIdx.x * blockDim.x + threadIdx.x;
    if (i < NN) { g_alive[i] = 1; g_list[0][i] = i; g_deg_in[i] = 0; g_deg_out[i] = 0; }
    if (i < HB) g_hist[i] = 0;
    if (i < 128) g_mean[i] = 0.f;
    if (i < 3 * 128) g_bmax[i] = __int_as_float(0xff800000);
    if (i == 0) { g_total = 0; g_selcnt = 0; g_candcnt = 0; g_e1n = 0; g_e2n = 0; }
}
// block 0: all alive; record per-dst ordinal for atomic-free scatter
__global__ void k_degree0(const int* __restrict__ src, const int* __restrict__ dst) {
    int i = blockIdx.x * blockDim.x + threadIdx.x;
    if (i >= EE) return;
    atomicAdd(&g_deg_out[src[i]], 1);
    g_ord[i] = atomicAdd(&g_deg_in[dst[i]], 1);
}
// blocks 1/2: filter, count, append (s,d,ord) warp-aggregated
__global__ void k_degcomp(const int* __restrict__ es, const int* __restrict__ ed, int mode) {
    int i = blockIdx.x * blockDim.x + threadIdx.x;
    int cnt = (mode == 1) ? EE : g_e1n;
    int s = 0, d = 0, od = 0; bool ok = false;
    if (i < cnt) {
        if (mode == 1) { s = es[i]; d = ed[i]; }
        else           { s = g_e1s[i]; d = g_e1d[i]; }
        ok = g_alive[s] && g_alive[d];
    }
    if (ok) { atomicAdd(&g_deg_out[s], 1); od = atomicAdd(&g_deg_in[d], 1); }
    unsigned m = __ballot_sync(~0u, ok);
    if (m) {
        int lane = threadIdx.x & 31;
        int ldr = __ffs(m) - 1;
        int base;
        if (lane == ldr) base = atomicAdd((mode == 1) ? &g_e1n : &g_e2n, __popc(m));
        base = __shfl_sync(~0u, base, ldr);
        if (ok) {
            int p = base + __popc(m & ((1u << lane) - 1));
            if (mode == 1) { g_e1s[p] = s; g_e1d[p] = d; g_e1o[p] = od; }
            else           { g_e2s[p] = s; g_e2d[p] = d; g_e2o[p] = od; }
        }
    }
}
// warp-aggregated CSR segment allocation + norm factors (alive only)
__global__ void k_alloc() {
    int i = blockIdx.x * blockDim.x + threadIdx.x;
    int lane = threadIdx.x & 31;
    int alive = (i < NN) ? g_alive[i] : 0;
    int d = alive ? g_deg_in[i] : 0;
    int x = d;
#pragma unroll
    for (int o = 1; o < 32; o <<= 1) { int t = __shfl_up_sync(~0u, x, o); if (lane >= o) x += t; }
    int base;
    if (lane == 31) base = atomicAdd(&g_total, x);
    base = __shfl_sync(~0u, base, 31);
    if (alive) {
        g_rowptr[i] = base + x - d;
        g_ns[i] = 1.0f / sqrtf(fmaxf((float)g_deg_out[i], 1.0f));
        g_nd[i] = 1.0f / sqrtf(fmaxf((float)d, 1.0f));
    }
}
// atomic-free scatter using recorded ordinals
__global__ void k_scatter(const int* __restrict__ es, const int* __restrict__ ed, int mode) {
    int i = blockIdx.x * blockDim.x + threadIdx.x;
    int cnt = (mode == 0) ? EE : (mode == 1 ? g_e1n : g_e2n);
    if (i >= cnt) return;
    int s, d, od;
    if (mode == 0)      { s = es[i];    d = ed[i];    od = g_ord[i]; }
    else if (mode == 1) { s = g_e1s[i]; d = g_e1d[i]; od = g_e1o[i]; }
    else                { s = g_e2s[i]; d = g_e2d[i]; od = g_e2o[i]; }
    g_csr[g_rowptr[d] + od] = s;
}
// hs[v] = (x[v] @ W) * ns[v] * (useTh ? th[v] : 1); x==null means g_hrelu
__global__ __launch_bounds__(256) void k_gemm(const float* __restrict__ x,
                                              const float* __restrict__ W,
                                              int lin, int nA, int useTh) {
    __shared__ float xs[64][128];
    __shared__ int rid[64];
    const float* xp = x ? x : (const float*)g_hrelu;
    int tid = threadIdx.x;
    if (tid < 64) {
        int r = blockIdx.x * 64 + tid;
        rid[tid] = (r < nA) ? g_list[lin][r] : -1;
    }
    __syncthreads();
    for (int i = tid; i < 2048; i += 256) {
        int row = i >> 5, c4 = i & 31;
        int v = rid[row];
        float4 xv = make_float4(0.f, 0.f, 0.f, 0.f);
        if (v >= 0) xv = *(const float4*)&xp[v * 128 + c4 * 4];
        *(float4*)&xs[row][c4 * 4] = xv;
    }
    __syncthreads();
    int cg = tid & 31, rg = tid >> 5;
    float acc[8][4];
#pragma unroll
    for (int j = 0; j < 8; j++) { acc[j][0] = 0.f; acc[j][1] = 0.f; acc[j][2] = 0.f; acc[j][3] = 0.f; }
#pragma unroll 4
    for (int k = 0; k < 128; k++) {
        float4 w = *(const float4*)&W[k * 128 + cg * 4];
#pragma unroll
        for (int j = 0; j < 8; j++) {
            float xv = xs[rg * 8 + j][k];
            acc[j][0] += xv * w.x; acc[j][1] += xv * w.y;
            acc[j][2] += xv * w.z; acc[j][3] += xv * w.w;
        }
    }
#pragma unroll
    for (int j = 0; j < 8; j++) {
        int v = rid[rg * 8 + j];
        if (v >= 0) {
            float s = g_ns[v] * (useTh ? g_th[v] : 1.0f);
            float4 o = make_float4(acc[j][0] * s, acc[j][1] * s, acc[j][2] * s, acc[j][3] * s);
            *(float4*)&g_hs[v * 128 + cg * 4] = o;
        }
    }
}
__global__ __launch_bounds__(256) void k_spmm_conv(const float* __restrict__ cb,
                                                   const float* __restrict__ sW,
                                                   int lin, int nA) {
    int gw = (blockIdx.x * blockDim.x + threadIdx.x) >> 5;
    int lane = threadIdx.x & 31;
    if (gw >= nA) return;
    int v = g_list[lin][gw];
    int s = g_rowptr[v], e = s + g_deg_in[v];
    float a0 = 0.f, a1 = 0.f, a2 = 0.f, a3 = 0.f;
    for (int i = s; i < e; i++) {
        int u = g_csr[i];
        float4 h = *(const float4*)&g_hs[u * 128 + lane * 4];
        a0 += h.x; a1 += h.y; a2 += h.z; a3 += h.w;
    }
    float ndv = g_nd[v];
    float4 b = *(const float4*)&cb[lane * 4];
    float4 hr;
    hr.x = fmaxf(fmaf(a0, ndv, b.x), 0.f);
    hr.y = fmaxf(fmaf(a1, ndv, b.y), 0.f);
    hr.z = fmaxf(fmaf(a2, ndv, b.z), 0.f);
    hr.w = fmaxf(fmaf(a3, ndv, b.w), 0.f);
    *(float4*)&g_hrelu[v * 128 + lane * 4] = hr;
    float4 w = *(const float4*)&sW[lane * 4];
    float sd = hr.x * w.x + hr.y * w.y + hr.z * w.z + hr.w * w.w;
#pragma unroll
    for (int o = 16; o; o >>= 1) sd += __shfl_down_sync(~0u, sd, o);
    if (lane == 0) g_hs2[v] = sd * g_ns[v];
}
// score + key + histogram in one pass
__global__ __launch_bounds__(256) void k_spmm_score(const float* __restrict__ sb,
                                                    int lin, int nA) {
    int gw = (blockIdx.x * blockDim.x + threadIdx.x) >> 5;
    int lane = threadIdx.x & 31;
    if (gw >= nA) return;
    int v = g_list[lin][gw];
    int s = g_rowptr[v], e = s + g_deg_in[v];
    float sum = 0.f;
    for (int i = s + lane; i < e; i += 32) sum += g_hs2[g_csr[i]];
#pragma unroll
    for (int o = 16; o; o >>= 1) sum += __shfl_down_sync(~0u, sum, o);
    if (lane == 0) {
        float sc = fmaf(sum, g_nd[v], sb[0]);
        g_score[v] = sc;
        unsigned kk = okey(sc);
        g_key[v] = kk;
        atomicAdd(&g_hist[kk >> 16], 1);
    }
}
// single block: find 16-bit bucket containing the k-th largest key
__global__ __launch_bounds__(1024) void k_pick(int k) {
    __shared__ int A[1024];
    int t = threadIdx.x;
    int base = t * 64;
    int s = 0;
#pragma unroll 8
    for (int b = 0; b < 64; b++) s += g_hist[base + b];
    A[t] = s;
    __syncthreads();
    for (int off = 1; off < 1024; off <<= 1) {
        int w = A[t] + ((t + off < 1024) ? A[t + off] : 0);
        __syncthreads();
        A[t] = w;
        __syncthreads();
    }
    int above = A[t] - s;
    if (above < k && above + s >= k) {
        int cum = above;
        for (int b = 63; b >= 0; b--) {
            int h = g_hist[base + b];
            if (cum + h >= k) { g_bucketHi = base + b; g_cntAbove = cum; break; }
            cum += h;
        }
    }
}
__global__ void k_cand(int lin, int lout, int nA) {
    int i = blockIdx.x * blockDim.x + threadIdx.x;
    int bh = g_bucketHi;
    int v = -1; unsigned key = 0; int hi = -1;
    if (i < nA) { v = g_list[lin][i]; key = g_key[v]; hi = (int)(key >> 16); }
    bool gt = (i < nA) && (hi > bh);
    bool eq = (i < nA) && (hi == bh);
    int lane = threadIdx.x & 31;
    unsigned m = __ballot_sync(~0u, gt);
    if (m) {
        int ldr = __ffs(m) - 1; int base;
        if (lane == ldr) base = atomicAdd(&g_selcnt, __popc(m));
        base = __shfl_sync(~0u, base, ldr);
        if (gt) g_list[lout][base + __popc(m & ((1u << lane) - 1))] = v;
    }
    unsigned m2 = __ballot_sync(~0u, eq);
    if (m2) {
        int ldr = __ffs(m2) - 1; int base;
        if (lane == ldr) base = atomicAdd(&g_candcnt, __popc(m2));
        base = __shfl_sync(~0u, base, ldr);
        if (eq) {
            int p = base + __popc(m2 & ((1u << lane) - 1));
            g_candk[p] = key; g_candv[p] = v;
        }
    }
    if (i < nA && !gt && !eq) g_alive[v] = 0;
}
// single block: refine low 16 bits over candidates, ties by lowest id
__global__ __launch_bounds__(1024) void k_finish(int lout, int k) {
    __shared__ int hist[256];
    __shared__ int sh_b1, sh_rem1, sh_b0, sh_needed, sh_tc;
    __shared__ int tiebuf[TCAP];
    int tid = threadIdx.x;
    int C = g_candcnt;
    int kp = k - g_cntAbove;
    for (int i = tid; i < 256; i += 1024) hist[i] = 0;
    if (tid == 0) sh_tc = 0;
    __syncthreads();
    for (int i = tid; i < C; i += 1024) atomicAdd(&hist[(g_candk[i] >> 8) & 255], 1);
    __syncthreads();
    if (tid == 0) {
        int cum = 0;
        for (int b = 255; b >= 0; b--) {
            int h = hist[b];
            if (cum + h >= kp) { sh_b1 = b; sh_rem1 = kp - cum; break; }
            cum += h;
        }
    }
    __syncthreads();
    int b1 = sh_b1, rem1 = sh_rem1;
    for (int i = tid; i < 256; i += 1024) hist[i] = 0;
    __syncthreads();
    for (int i = tid; i < C; i += 1024) {
        unsigned kk = g_candk[i];
        if ((int)((kk >> 8) & 255) == b1) atomicAdd(&hist[kk & 255], 1);
    }
    __syncthreads();
    if (tid == 0) {
        int cum = 0;
        for (int b = 255; b >= 0; b--) {
            int h = hist[b];
            if (cum + h >= rem1) { sh_b0 = b; sh_needed = rem1 - cum; break; }
            cum += h;
        }
    }
    __syncthreads();
    unsigned lo_t = ((unsigned)b1 << 8) | (unsigned)sh_b0;
    int needed = sh_needed;
    for (int i = tid; i < C; i += 1024) {
        unsigned lo = g_candk[i] & 0xFFFFu;
        int v = g_candv[i];
        if (lo > lo_t) {
            int p = atomicAdd(&g_selcnt, 1);
            g_list[lout][p] = v;
        } else if (lo < lo_t) {
            g_alive[v] = 0;
        } else {
            int p = atomicAdd(&sh_tc, 1);
            if (p < TCAP) tiebuf[p] = v;
        }
    }
    __syncthreads();
    int T = sh_tc;
    if (T <= needed) {
        for (int i = tid; i < C; i += 1024) {
            if ((g_candk[i] & 0xFFFFu) == lo_t) {
                int p = atomicAdd(&g_selcnt, 1);
                g_list[lout][p] = g_candv[i];
            }
        }
    } else if (T <= TCAP) {
        for (int j = tid; j < T; j += 1024) {
            int vj = tiebuf[j];
            int r = 0;
            for (int q = 0; q < T; q++) r += (tiebuf[q] < vj);
            if (r < needed) {
                int p = atomicAdd(&g_selcnt, 1);
                g_list[lout][p] = vj;
            } else g_alive[vj] = 0;
        }
    } else {
        for (int i = tid; i < C; i += 1024) {
            if ((g_candk[i] & 0xFFFFu) != lo_t) continue;
            int vi = g_candv[i];
            int r = 0;
            for (int q = 0; q < C; q++)
                if ((g_candk[q] & 0xFFFFu) == lo_t && g_candv[q] < vi) r++;
            if (r < needed) {
                int p = atomicAdd(&g_selcnt, 1);
                g_list[lout][p] = vi;
            } else g_alive[vi] = 0;
        }
    }
}
// readout + th store + next-block state zeroing (deg of selected, hist, counters)
__global__ __launch_bounds__(128) void k_pool(int b, int lout, int kb, float invk, int doZero) {
    __shared__ float sth[64];
    __shared__ int sv[64];
    int c = threadIdx.x;
    int base = blockIdx.x * 64;
    int lim = min(64, kb - base);
    if (c < 64 && c < lim) {
        int v = g_list[lout][base + c];
        float th = tanhf(g_score[v]);
        sth[c] = th; sv[c] = v; g_th[v] = th;
        if (doZero) { g_deg_in[v] = 0; g_deg_out[v] = 0; }
    }
    if (doZero) {
        for (int i = blockIdx.x * blockDim.x + c; i < HB; i += gridDim.x * blockDim.x) g_hist[i] = 0;
        if (base == 0 && c == 0) {
            g_total = 0; g_selcnt = 0; g_candcnt = 0;
            if (b == 0) g_e1n = 0; else g_e2n = 0;
        }
    }
    __syncthreads();
    float msum = 0.f, mmax = __int_as_float(0xff800000);
    for (int j = 0; j < lim; j++) {
        float val = g_hrelu[sv[j] * 128 + c] * sth[j];
        msum += val;
        mmax = fmaxf(mmax, val);
    }
    atomicAdd(&g_mean[c], msum * invk);
    atomicMaxF(&g_bmax[b * 128 + c], mmax);
}
// lin1 with inline assembly of the 1280-dim input
__global__ __launch_bounds__(1024) void k_lin1(const float* __restrict__ seq,
                                               const float* __restrict__ W,
                                               const float* __restrict__ b) {
    __shared__ float fin[1280];
    __shared__ float red[1024];
    int t = threadIdx.x;
    for (int i = t; i < 1280; i += 1024) {
        float v;
        if (i < 128)      v = g_mean[i];
        else if (i < 256) v = g_bmax[i - 128] + g_bmax[128 + (i - 128)] + g_bmax[256 + (i - 128)];
        else              v = seq[i - 256];
        fin[i] = v;
    }
    __syncthreads();
    int o = t & 255, part = t >> 8;
    float acc = 0.f;
    int k0 = part * 320;
    for (int k = k0; k < k0 + 320; k++) acc = fmaf(fin[k], W[k * 256 + o], acc);
    red[t] = acc;
    __syncthreads();
    if (t < 256) {
        float s = red[t] + red[t + 256] + red[t + 512] + red[t + 768] + b[t];
        g_f1[t] = fmaxf(s, 0.f);
    }
}
// fused lin2 (relu) + lin3, single block
__global__ __launch_bounds__(1024) void k_lin23(const float* __restrict__ W2, const float* __restrict__ b2,
                                                const float* __restrict__ W3, const float* __restrict__ b3,
                                                float* __restrict__ out) {
    __shared__ float f1[256];
    __shared__ float f2[128];
    int t = threadIdx.x;
    if (t < 256) f1[t] = g_f1[t];
    __syncthreads();
    if (t < 128) {
        float acc = b2[t];
        for (int k = 0; k < 256; k++) acc = fmaf(f1[k], W2[k * 128 + t], acc);
        f2[t] = fmaxf(acc, 0.f);
    }
    __syncthreads();
#pragma unroll
    for (int r = 0; r < 2; r++) {
        int o = t + r * 1024;
        float acc = b3[o];
        for (int k = 0; k < 128; k++) acc = fmaf(f2[k], W3[k * 2048 + o], acc);
        out[o] = acc;
    }
}

extern "C" void kernel_launch(void* const* d_in, const int* in_sizes, int n_in,
                              void* d_out, int out_size) {
    const float* feat = (const float*)d_in[0];
    const float* seq  = (const float*)d_in[1];
    const int*   src  = (const int*)d_in[2];
    const int*   dst  = (const int*)d_in[3];
    const float* cW[3] = {(const float*)d_in[6],  (const float*)d_in[10], (const float*)d_in[14]};
    const float* cb[3] = {(const float*)d_in[7],  (const float*)d_in[11], (const float*)d_in[15]};
    const float* sW[3] = {(const float*)d_in[8],  (const float*)d_in[12], (const float*)d_in[16]};
    const float* sb[3] = {(const float*)d_in[9],  (const float*)d_in[13], (const float*)d_in[17]};
    const float* l1W = (const float*)d_in[18];
    const float* l1b = (const float*)d_in[19];
    const float* l2W = (const float*)d_in[20];
    const float* l2b = (const float*)d_in[21];
    const float* l3W = (const float*)d_in[22];
    const float* l3b = (const float*)d_in[23];
    float* out = (float*)d_out;

    const int nAv[3] = {50000, 25000, 12500};
    const int kbv[3] = {25000, 12500, 6250};
    const int EGRID = (EE + 255) / 256;

    k_init0<<<(HB + 255) / 256, 256>>>();
    for (int b = 0; b < 3; b++) {
        int nA = nAv[b], kb = kbv[b];
        int lin = b & 1, lout = 1 - lin;
        if (b == 0) k_degree0<<<EGRID, 256>>>(src, dst);
        else        k_degcomp<<<EGRID, 256>>>(src, dst, b);
        k_alloc<<<(NN + 255) / 256, 256>>>();
        k_gemm<<<(nA + 63) / 64, 256>>>(b == 0 ? feat : (const float*)0, cW[b], lin, nA, b > 0);
        k_scatter<<<EGRID, 256>>>(src, dst, b);
        k_spmm_conv<<<(nA + 7) / 8, 256>>>(cb[b], sW[b], lin, nA);
        k_spmm_score<<<(nA + 7) / 8, 256>>>(sb[b], lin, nA);
        k_pick<<<1, 1024>>>(kb);
        k_cand<<<(nA + 255) / 256, 256>>>(lin, lout, nA);
        k_finish<<<1, 1024>>>(lout, kb);
        k_pool<<<(kb + 63) / 64, 128>>>(b, lout, kb, 1.0f / (float)kb, b < 2);
    }
    k_lin1<<<1, 1024>>>(seq, l1W, l1b);
    k_lin23<<<1, 1024>>>(l2W, l2b, l3W, l3b, out);
}

// round 7
// speedup vs baseline: 2.1172x; 1.2767x over previous
// SAGNetworkHierarchical GB300 kernel, round 7.
// R6: 497.7 us, gemm profiled at 68.5us / fma 31% / issue 42% -> LDS-bound.
// This round: gemm k-step-4 float4-LDS (broadcast) restructure, spmm csr
// shuffle prefetch, k_pick int4-vectorized histogram read.
#include <cuda_runtime.h>
#include <math.h>

#define NN 50000
#define EE 800000
#define HB 65536
#define TCAP 6144

__device__ float    g_hs[NN * 128];
__device__ float    g_hrelu[NN * 128];
__device__ float    g_hs2[NN];
__device__ float    g_score[NN];
__device__ float    g_th[NN];
__device__ unsigned g_key[NN];
__device__ int      g_deg_in[NN];
__device__ int      g_deg_out[NN];
__device__ int      g_rowptr[NN];
__device__ int      g_csr[EE];
__device__ int      g_ord[EE];
__device__ int      g_alive[NN];
__device__ int      g_list[2][NN];
__device__ float    g_ns[NN];
__device__ float    g_nd[NN];
__device__ float    g_mean[128];
__device__ float    g_bmax[3 * 128];
__device__ int      g_total;
__device__ int      g_hist[HB];
__device__ int      g_bucketHi;
__device__ int      g_cntAbove;
__device__ int      g_selcnt;
__device__ int      g_candcnt;
__device__ unsigned g_candk[NN];
__device__ int      g_candv[NN];
__device__ int      g_e1s[EE], g_e1d[EE], g_e1o[EE];
__device__ int      g_e2s[EE], g_e2d[EE], g_e2o[EE];
__device__ int      g_e1n, g_e2n;
__device__ float    g_f1[256];

__device__ __forceinline__ unsigned okey(float f) {
    unsigned u = __float_as_uint(f);
    return (u & 0x80000000u) ? ~u : (u | 0x80000000u);
}
__device__ __forceinline__ void atomicMaxF(float* a, float v) {
    if (v >= 0.f) atomicMax((int*)a, __float_as_int(v));
    else          atomicMin((unsigned*)a, __float_as_uint(v));
}

__global__ void k_init0() {
    int i = blockIdx.x * blockDim.x + threadIdx.x;
    if (i < NN) { g_alive[i] = 1; g_list[0][i] = i; g_deg_in[i] = 0; g_deg_out[i] = 0; }
    if (i < HB) g_hist[i] = 0;
    if (i < 128) g_mean[i] = 0.f;
    if (i < 3 * 128) g_bmax[i] = __int_as_float(0xff800000);
    if (i == 0) { g_total = 0; g_selcnt = 0; g_candcnt = 0; g_e1n = 0; g_e2n = 0; }
}
__global__ void k_degree0(const int* __restrict__ src, const int* __restrict__ dst) {
    int i = blockIdx.x * blockDim.x + threadIdx.x;
    if (i >= EE) return;
    atomicAdd(&g_deg_out[src[i]], 1);
    g_ord[i] = atomicAdd(&g_deg_in[dst[i]], 1);
}
__global__ void k_degcomp(const int* __restrict__ es, const int* __restrict__ ed, int mode) {
    int i = blockIdx.x * blockDim.x + threadIdx.x;
    int cnt = (mode == 1) ? EE : g_e1n;
    int s = 0, d = 0, od = 0; bool ok = false;
    if (i < cnt) {
        if (mode == 1) { s = es[i]; d = ed[i]; }
        else           { s = g_e1s[i]; d = g_e1d[i]; }
        ok = g_alive[s] && g_alive[d];
    }
    if (ok) { atomicAdd(&g_deg_out[s], 1); od = atomicAdd(&g_deg_in[d], 1); }
    unsigned m = __ballot_sync(~0u, ok);
    if (m) {
        int lane = threadIdx.x & 31;
        int ldr = __ffs(m) - 1;
        int base;
        if (lane == ldr) base = atomicAdd((mode == 1) ? &g_e1n : &g_e2n, __popc(m));
        base = __shfl_sync(~0u, base, ldr);
        if (ok) {
            int p = base + __popc(m & ((1u << lane) - 1));
            if (mode == 1) { g_e1s[p] = s; g_e1d[p] = d; g_e1o[p] = od; }
            else           { g_e2s[p] = s; g_e2d[p] = d; g_e2o[p] = od; }
        }
    }
}
__global__ void k_alloc() {
    int i = blockIdx.x * blockDim.x + threadIdx.x;
    int lane = threadIdx.x & 31;
    int alive = (i < NN) ? g_alive[i] : 0;
    int d = alive ? g_deg_in[i] : 0;
    int x = d;
#pragma unroll
    for (int o = 1; o < 32; o <<= 1) { int t = __shfl_up_sync(~0u, x, o); if (lane >= o) x += t; }
    int base;
    if (lane == 31) base = atomicAdd(&g_total, x);
    base = __shfl_sync(~0u, base, 31);
    if (alive) {
        g_rowptr[i] = base + x - d;
        g_ns[i] = 1.0f / sqrtf(fmaxf((float)g_deg_out[i], 1.0f));
        g_nd[i] = 1.0f / sqrtf(fmaxf((float)d, 1.0f));
    }
}
__global__ void k_scatter(const int* __restrict__ es, const int* __restrict__ ed, int mode) {
    int i = blockIdx.x * blockDim.x + threadIdx.x;
    int cnt = (mode == 0) ? EE : (mode == 1 ? g_e1n : g_e2n);
    if (i >= cnt) return;
    int s, d, od;
    if (mode == 0)      { s = es[i];    d = ed[i];    od = g_ord[i]; }
    else if (mode == 1) { s = g_e1s[i]; d = g_e1d[i]; od = g_e1o[i]; }
    else                { s = g_e2s[i]; d = g_e2d[i]; od = g_e2o[i]; }
    g_csr[g_rowptr[d] + od] = s;
}
// hs[v] = (x[v] @ W) * ns[v] * (useTh ? th[v] : 1); x==null means g_hrelu.
// Inner loop: k in steps of 4, xs read as float4 (warp-broadcast LDS.128),
// W staged as 4 float4 LDGs -> 12 loads per 128 FMA.
__global__ __launch_bounds__(256, 3) void k_gemm(const float* __restrict__ x,
                                                 const float* __restrict__ W,
                                                 int lin, int nA, int useTh) {
    __shared__ float xs[64][128];
    __shared__ int rid[64];
    const float* xp = x ? x : (const float*)g_hrelu;
    int tid = threadIdx.x;
    if (tid < 64) {
        int r = blockIdx.x * 64 + tid;
        rid[tid] = (r < nA) ? g_list[lin][r] : -1;
    }
    __syncthreads();
    for (int i = tid; i < 2048; i += 256) {
        int row = i >> 5, c4 = i & 31;
        int v = rid[row];
        float4 xv = make_float4(0.f, 0.f, 0.f, 0.f);
        if (v >= 0) xv = *(const float4*)&xp[v * 128 + c4 * 4];
        *(float4*)&xs[row][c4 * 4] = xv;
    }
    __syncthreads();
    int cg = tid & 31, rg = tid >> 5;
    float4 acc[8];
#pragma unroll
    for (int j = 0; j < 8; j++) acc[j] = make_float4(0.f, 0.f, 0.f, 0.f);
#pragma unroll 8
    for (int k0 = 0; k0 < 128; k0 += 4) {
        float4 w0 = *(const float4*)&W[(k0 + 0) * 128 + cg * 4];
        float4 w1 = *(const float4*)&W[(k0 + 1) * 128 + cg * 4];
        float4 w2 = *(const float4*)&W[(k0 + 2) * 128 + cg * 4];
        float4 w3 = *(const float4*)&W[(k0 + 3) * 128 + cg * 4];
#pragma unroll
        for (int j = 0; j < 8; j++) {
            float4 xv = *(const float4*)&xs[rg * 8 + j][k0];
            acc[j].x = fmaf(xv.x, w0.x, acc[j].x); acc[j].y = fmaf(xv.x, w0.y, acc[j].y);
            acc[j].z = fmaf(xv.x, w0.z, acc[j].z); acc[j].w = fmaf(xv.x, w0.w, acc[j].w);
            acc[j].x = fmaf(xv.y, w1.x, acc[j].x); acc[j].y = fmaf(xv.y, w1.y, acc[j].y);
            acc[j].z = fmaf(xv.y, w1.z, acc[j].z); acc[j].w = fmaf(xv.y, w1.w, acc[j].w);
            acc[j].x = fmaf(xv.z, w2.x, acc[j].x); acc[j].y = fmaf(xv.z, w2.y, acc[j].y);
            acc[j].z = fmaf(xv.z, w2.z, acc[j].z); acc[j].w = fmaf(xv.z, w2.w, acc[j].w);
            acc[j].x = fmaf(xv.w, w3.x, acc[j].x); acc[j].y = fmaf(xv.w, w3.y, acc[j].y);
            acc[j].z = fmaf(xv.w, w3.z, acc[j].z); acc[j].w = fmaf(xv.w, w3.w, acc[j].w);
        }
    }
#pragma unroll
    for (int j = 0; j < 8; j++) {
        int v = rid[rg * 8 + j];
        if (v >= 0) {
            float s = g_ns[v] * (useTh ? g_th[v] : 1.0f);
            float4 o = make_float4(acc[j].x * s, acc[j].y * s, acc[j].z * s, acc[j].w * s);
            *(float4*)&g_hs[v * 128 + cg * 4] = o;
        }
    }
}
// warp per node; csr indices preloaded 32-at-a-time coalesced, shfl-broadcast
__global__ __launch_bounds__(256) void k_spmm_conv(const float* __restrict__ cb,
                                                   const float* __restrict__ sW,
                                                   int lin, int nA) {
    int gw = (blockIdx.x * blockDim.x + threadIdx.x) >> 5;
    int lane = threadIdx.x & 31;
    if (gw >= nA) return;
    int v = g_list[lin][gw];
    int s = g_rowptr[v];
    int nb = g_deg_in[v];
    float a0 = 0.f, a1 = 0.f, a2 = 0.f, a3 = 0.f;
    for (int i0 = 0; i0 < nb; i0 += 32) {
        int u32 = (i0 + lane < nb) ? g_csr[s + i0 + lane] : 0;
        int lim = min(32, nb - i0);
        for (int j = 0; j < lim; j++) {
            int u = __shfl_sync(~0u, u32, j);
            float4 h = *(const float4*)&g_hs[u * 128 + lane * 4];
            a0 += h.x; a1 += h.y; a2 += h.z; a3 += h.w;
        }
    }
    float ndv = g_nd[v];
    float4 b = *(const float4*)&cb[lane * 4];
    float4 hr;
    hr.x = fmaxf(fmaf(a0, ndv, b.x), 0.f);
    hr.y = fmaxf(fmaf(a1, ndv, b.y), 0.f);
    hr.z = fmaxf(fmaf(a2, ndv, b.z), 0.f);
    hr.w = fmaxf(fmaf(a3, ndv, b.w), 0.f);
    *(float4*)&g_hrelu[v * 128 + lane * 4] = hr;
    float4 w = *(const float4*)&sW[lane * 4];
    float sd = hr.x * w.x + hr.y * w.y + hr.z * w.z + hr.w * w.w;
#pragma unroll
    for (int o = 16; o; o >>= 1) sd += __shfl_down_sync(~0u, sd, o);
    if (lane == 0) g_hs2[v] = sd * g_ns[v];
}
__global__ __launch_bounds__(256) void k_spmm_score(const float* __restrict__ sb,
                                                    int lin, int nA) {
    int gw = (blockIdx.x * blockDim.x + threadIdx.x) >> 5;
    int lane = threadIdx.x & 31;
    if (gw >= nA) return;
    int v = g_list[lin][gw];
    int s = g_rowptr[v], e = s + g_deg_in[v];
    float sum = 0.f;
    for (int i = s + lane; i < e; i += 32) sum += g_hs2[g_csr[i]];
#pragma unroll
    for (int o = 16; o; o >>= 1) sum += __shfl_down_sync(~0u, sum, o);
    if (lane == 0) {
        float sc = fmaf(sum, g_nd[v], sb[0]);
        g_score[v] = sc;
        unsigned kk = okey(sc);
        g_key[v] = kk;
        atomicAdd(&g_hist[kk >> 16], 1);
    }
}
// single block: find 16-bit bucket containing the k-th largest key (int4 reads)
__global__ __launch_bounds__(1024) void k_pick(int k) {
    __shared__ int A[1024];
    int t = threadIdx.x;
    const int4* h4 = (const int4*)g_hist;
    int base4 = t * 16;
    int s = 0;
#pragma unroll
    for (int b = 0; b < 16; b++) {
        int4 v = h4[base4 + b];
        s += v.x + v.y + v.z + v.w;
    }
    A[t] = s;
    __syncthreads();
    for (int off = 1; off < 1024; off <<= 1) {
        int w = A[t] + ((t + off < 1024) ? A[t + off] : 0);
        __syncthreads();
        A[t] = w;
        __syncthreads();
    }
    int above = A[t] - s;
    if (above < k && above + s >= k) {
        int cum = above;
        int base = t * 64;
        for (int b = 63; b >= 0; b--) {
            int h = g_hist[base + b];
            if (cum + h >= k) { g_bucketHi = base + b; g_cntAbove = cum; break; }
            cum += h;
        }
    }
}
__global__ void k_cand(int lin, int lout, int nA) {
    int i = blockIdx.x * blockDim.x + threadIdx.x;
    int bh = g_bucketHi;
    int v = -1; unsigned key = 0; int hi = -1;
    if (i < nA) { v = g_list[lin][i]; key = g_key[v]; hi = (int)(key >> 16); }
    bool gt = (i < nA) && (hi > bh);
    bool eq = (i < nA) && (hi == bh);
    int lane = threadIdx.x & 31;
    unsigned m = __ballot_sync(~0u, gt);
    if (m) {
        int ldr = __ffs(m) - 1; int base;
        if (lane == ldr) base = atomicAdd(&g_selcnt, __popc(m));
        base = __shfl_sync(~0u, base, ldr);
        if (gt) g_list[lout][base + __popc(m & ((1u << lane) - 1))] = v;
    }
    unsigned m2 = __ballot_sync(~0u, eq);
    if (m2) {
        int ldr = __ffs(m2) - 1; int base;
        if (lane == ldr) base = atomicAdd(&g_candcnt, __popc(m2));
        base = __shfl_sync(~0u, base, ldr);
        if (eq) {
            int p = base + __popc(m2 & ((1u << lane) - 1));
            g_candk[p] = key; g_candv[p] = v;
        }
    }
    if (i < nA && !gt && !eq) g_alive[v] = 0;
}
__global__ __launch_bounds__(1024) void k_finish(int lout, int k) {
    __shared__ int hist[256];
    __shared__ int sh_b1, sh_rem1, sh_b0, sh_needed, sh_tc;
    __shared__ int tiebuf[TCAP];
    int tid = threadIdx.x;
    int C = g_candcnt;
    int kp = k - g_cntAbove;
    for (int i = tid; i < 256; i += 1024) hist[i] = 0;
    if (tid == 0) sh_tc = 0;
    __syncthreads();
    for (int i = tid; i < C; i += 1024) atomicAdd(&hist[(g_candk[i] >> 8) & 255], 1);
    __syncthreads();
    if (tid == 0) {
        int cum = 0;
        for (int b = 255; b >= 0; b--) {
            int h = hist[b];
            if (cum + h >= kp) { sh_b1 = b; sh_rem1 = kp - cum; break; }
            cum += h;
        }
    }
    __syncthreads();
    int b1 = sh_b1, rem1 = sh_rem1;
    for (int i = tid; i < 256; i += 1024) hist[i] = 0;
    __syncthreads();
    for (int i = tid; i < C; i += 1024) {
        unsigned kk = g_candk[i];
        if ((int)((kk >> 8) & 255) == b1) atomicAdd(&hist[kk & 255], 1);
    }
    __syncthreads();
    if (tid == 0) {
        int cum = 0;
        for (int b = 255; b >= 0; b--) {
            int h = hist[b];
            if (cum + h >= rem1) { sh_b0 = b; sh_needed = rem1 - cum; break; }
            cum += h;
        }
    }
    __syncthreads();
    unsigned lo_t = ((unsigned)b1 << 8) | (unsigned)sh_b0;
    int needed = sh_needed;
    for (int i = tid; i < C; i += 1024) {
        unsigned lo = g_candk[i] & 0xFFFFu;
        int v = g_candv[i];
        if (lo > lo_t) {
            int p = atomicAdd(&g_selcnt, 1);
            g_list[lout][p] = v;
        } else if (lo < lo_t) {
            g_alive[v] = 0;
        } else {
            int p = atomicAdd(&sh_tc, 1);
            if (p < TCAP) tiebuf[p] = v;
        }
    }
    __syncthreads();
    int T = sh_tc;
    if (T <= needed) {
        for (int i = tid; i < C; i += 1024) {
            if ((g_candk[i] & 0xFFFFu) == lo_t) {
                int p = atomicAdd(&g_selcnt, 1);
                g_list[lout][p] = g_candv[i];
            }
        }
    } else if (T <= TCAP) {
        for (int j = tid; j < T; j += 1024) {
            int vj = tiebuf[j];
            int r = 0;
            for (int q = 0; q < T; q++) r += (tiebuf[q] < vj);
            if (r < needed) {
                int p = atomicAdd(&g_selcnt, 1);
                g_list[lout][p] = vj;
            } else g_alive[vj] = 0;
        }
    } else {
        for (int i = tid; i < C; i += 1024) {
            if ((g_candk[i] & 0xFFFFu) != lo_t) continue;
            int vi = g_candv[i];
            int r = 0;
            for (int q = 0; q < C; q++)
                if ((g_candk[q] & 0xFFFFu) == lo_t && g_candv[q] < vi) r++;
            if (r < needed) {
                int p = atomicAdd(&g_selcnt, 1);
                g_list[lout][p] = vi;
            } else g_alive[vi] = 0;
        }
    }
}
__global__ __launch_bounds__(128) void k_pool(int b, int lout, int kb, float invk, int doZero) {
    __shared__ float sth[64];
    __shared__ int sv[64];
    int c = threadIdx.x;
    int base = blockIdx.x * 64;
    int lim = min(64, kb - base);
    if (c < 64 && c < lim) {
        int v = g_list[lout][base + c];
        float th = tanhf(g_score[v]);
        sth[c] = th; sv[c] = v; g_th[v] = th;
        if (doZero) { g_deg_in[v] = 0; g_deg_out[v] = 0; }
    }
    if (doZero) {
        for (int i = blockIdx.x * blockDim.x + c; i < HB; i += gridDim.x * blockDim.x) g_hist[i] = 0;
        if (base == 0 && c == 0) {
            g_total = 0; g_selcnt = 0; g_candcnt = 0;
            if (b == 0) g_e1n = 0; else g_e2n = 0;
        }
    }
    __syncthreads();
    float msum = 0.f, mmax = __int_as_float(0xff800000);
    for (int j = 0; j < lim; j++) {
        float val = g_hrelu[sv[j] * 128 + c] * sth[j];
        msum += val;
        mmax = fmaxf(mmax, val);
    }
    atomicAdd(&g_mean[c], msum * invk);
    atomicMaxF(&g_bmax[b * 128 + c], mmax);
}
__global__ __launch_bounds__(1024) void k_lin1(const float* __restrict__ seq,
                                               const float* __restrict__ W,
                                               const float* __restrict__ b) {
    __shared__ float fin[1280];
    __shared__ float red[1024];
    int t = threadIdx.x;
    for (int i = t; i < 1280; i += 1024) {
        float v;
        if (i < 128)      v = g_mean[i];
        else if (i < 256) v = g_bmax[i - 128] + g_bmax[128 + (i - 128)] + g_bmax[256 + (i - 128)];
        else              v = seq[i - 256];
        fin[i] = v;
    }
    __syncthreads();
    int o = t & 255, part = t >> 8;
    float acc = 0.f;
    int k0 = part * 320;
    for (int k = k0; k < k0 + 320; k++) acc = fmaf(fin[k], W[k * 256 + o], acc);
    red[t] = acc;
    __syncthreads();
    if (t < 256) {
        float s = red[t] + red[t + 256] + red[t + 512] + red[t + 768] + b[t];
        g_f1[t] = fmaxf(s, 0.f);
    }
}
__global__ __launch_bounds__(1024) void k_lin23(const float* __restrict__ W2, const float* __restrict__ b2,
                                                const float* __restrict__ W3, const float* __restrict__ b3,
                                                float* __restrict__ out) {
    __shared__ float f1[256];
    __shared__ float f2[128];
    int t = threadIdx.x;
    if (t < 256) f1[t] = g_f1[t];
    __syncthreads();
    if (t < 128) {
        float acc = b2[t];
        for (int k = 0; k < 256; k++) acc = fmaf(f1[k], W2[k * 128 + t], acc);
        f2[t] = fmaxf(acc, 0.f);
    }
    __syncthreads();
#pragma unroll
    for (int r = 0; r < 2; r++) {
        int o = t + r * 1024;
        float acc = b3[o];
        for (int k = 0; k < 128; k++) acc = fmaf(f2[k], W3[k * 2048 + o], acc);
        out[o] = acc;
    }
}

extern "C" void kernel_launch(void* const* d_in, const int* in_sizes, int n_in,
                              void* d_out, int out_size) {
    const float* feat = (const float*)d_in[0];
    const float* seq  = (const float*)d_in[1];
    const int*   src  = (const int*)d_in[2];
    const int*   dst  = (const int*)d_in[3];
    const float* cW[3] = {(const float*)d_in[6],  (const float*)d_in[10], (const float*)d_in[14]};
    const float* cb[3] = {(const float*)d_in[7],  (const float*)d_in[11], (const float*)d_in[15]};
    const float* sW[3] = {(const float*)d_in[8],  (const float*)d_in[12], (const float*)d_in[16]};
    const float* sb[3] = {(const float*)d_in[9],  (const float*)d_in[13], (const float*)d_in[17]};
    const float* l1W = (const float*)d_in[18];
    const float* l1b = (const float*)d_in[19];
    const float* l2W = (const float*)d_in[20];
    const float* l2b = (const float*)d_in[21];
    const float* l3W = (const float*)d_in[22];
    const float* l3b = (const float*)d_in[23];
    float* out = (float*)d_out;

    const int nAv[3] = {50000, 25000, 12500};
    const int kbv[3] = {25000, 12500, 6250};
    const int EGRID = (EE + 255) / 256;

    k_init0<<<(HB + 255) / 256, 256>>>();
    for (int b = 0; b < 3; b++) {
        int nA = nAv[b], kb = kbv[b];
        int lin = b & 1, lout = 1 - lin;
        if (b == 0) k_degree0<<<EGRID, 256>>>(src, dst);
        else        k_degcomp<<<EGRID, 256>>>(src, dst, b);
        k_alloc<<<(NN + 255) / 256, 256>>>();
        k_gemm<<<(nA + 63) / 64, 256>>>(b == 0 ? feat : (const float*)0, cW[b], lin, nA, b > 0);
        k_scatter<<<EGRID, 256>>>(src, dst, b);
        k_spmm_conv<<<(nA + 7) / 8, 256>>>(cb[b], sW[b], lin, nA);
        k_spmm_score<<<(nA + 7) / 8, 256>>>(sb[b], lin, nA);
        k_pick<<<1, 1024>>>(kb);
        k_cand<<<(nA + 255) / 256, 256>>>(lin, lout, nA);
        k_finish<<<1, 1024>>>(lout, kb);
        k_pool<<<(kb + 63) / 64, 128>>>(b, lout, kb, 1.0f / (float)kb, b < 2);
    }
    k_lin1<<<1, 1024>>>(seq, l1W, l1b);
    k_lin23<<<1, 1024>>>(l2W, l2b, l3W, l3b, out);
}